// round 12
// baseline (speedup 1.0000x reference)
#include <cuda_runtime.h>
#include <stdint.h>
#include <math.h>

#define HID 1024
#define NE 64
#define MAXBS 1024
#define EPCAP 1024
#define TB 32            // tokens per phaseB chunk
#define NCI 16           // c-iterations (KCB=64 floats = 16 float4)
#define NSTGA 4          // phaseA pipeline depth
#define NSTGB 3          // phaseB pipeline depth
#define GRIDY 6          // phaseB y-blocks per (expert,half)

// phaseA dynamic smem layout (bytes)
#define WSA_BYTES (NSTGA * 64 * 17 * 16)        // 69632
#define XSA_BYTES (NSTGA * 8 * 17 * 16)         // 8704
#define LG_BYTES  (8 * 64 * 4)                  // 2048
#define SMEM_A (WSA_BYTES + XSA_BYTES + LG_BYTES)

// phaseB dynamic smem layout (bytes): 32 rows per block (row-split)
#define WS_BYTES (NSTGB * 32 * 17 * 16)         // 26112
#define XS_BYTES (NSTGB * TB * 17 * 16)         // 26112
#define TL_BYTES (EPCAP * 4)                    // 4096
#define SMEM_B (WS_BYTES + XS_BYTES + TL_BYTES) // 56320 -> 4 blocks/SM

// ---- device scratch (allocation-free) ----
__device__ int   g_slotexp[MAXBS * 4];  // [token*4+slot] -> expert id
__device__ int   g_prog[MAXBS];         // per-token completion counter
__device__ int   g_pcnt[MAXBS * 4];     // per-pair half-completion counter
__device__ int   g_ids[MAXBS * 12];     // per-token candidate ids (masked = -10000)
__device__ float g_res[MAXBS * 4 * 64]; // per-pair row results: [pair][0-31 gate |32-63 up]

__device__ __forceinline__ void cp16(unsigned int dst, const void* src) {
    asm volatile("cp.async.cg.shared.global [%0], [%1], 16;" :: "r"(dst), "l"(src));
}
__device__ __forceinline__ void cp16p(unsigned int dst, const void* src, int valid) {
    asm volatile("cp.async.cg.shared.global [%0], [%1], 16, %2;"
                 :: "r"(dst), "l"(src), "r"(valid ? 16 : 0));
}
__device__ __forceinline__ void cp_commit() { asm volatile("cp.async.commit_group;"); }
__device__ __forceinline__ void cp_wait1() { asm volatile("cp.async.wait_group 1;"); }
__device__ __forceinline__ void cp_wait2() { asm volatile("cp.async.wait_group 2;"); }
__device__ __forceinline__ unsigned int smem_u32(const void* p) {
    return (unsigned int)__cvta_generic_to_shared(p);
}
__device__ __forceinline__ void fma2(unsigned long long& acc,
                                     unsigned long long a, unsigned long long b) {
    asm("fma.rn.f32x2 %0, %1, %2, %0;" : "+l"(acc) : "l"(a), "l"(b));
}
__device__ __forceinline__ float unpack_sum(unsigned long long lo, unsigned long long hi) {
    float s0, s1, s2, s3;
    asm("mov.b64 {%0,%1}, %2;" : "=f"(s0), "=f"(s1) : "l"(lo));
    asm("mov.b64 {%0,%1}, %2;" : "=f"(s2), "=f"(s3) : "l"(hi));
    return (s0 + s1) + (s2 + s3);
}

// ============================================================
// Phase A: router GEMM (8 tokens/block), 4-stage cp.async
// pipeline; top-4 + renorm; writes final_weights, slot map,
// zeroes g_prog + g_pcnt.
// ============================================================
__global__ __launch_bounds__(256) void phaseA(const float* __restrict__ x,
                                              const float* __restrict__ wg,
                                              float* __restrict__ outw,
                                              int bs) {
    extern __shared__ char dsa[];
    float4 (*ws4)[64][17] = reinterpret_cast<float4(*)[64][17]>(dsa);
    float4 (*xs4)[8][17]  = reinterpret_cast<float4(*)[8][17]>(dsa + WSA_BYTES);
    float  (*lg)[64]      = reinterpret_cast<float(*)[64]>(dsa + WSA_BYTES + XSA_BYTES);

    int t  = threadIdx.x;
    int r  = t & 63;
    int tg = t >> 6;
    int tok0 = blockIdx.x * 8;

    int wrow = t >> 4;
    int wcol = t & 15;
    int xtok = tok0 + wrow - 8;
    int do_x = (wrow >= 8) && (wrow < 16);
    const float4* xsrcA = reinterpret_cast<const float4*>(x) +
        ((do_x && xtok < bs) ? (size_t)xtok * (HID / 4) : 0);
    int xvalid = do_x && (xtok < bs);

    #pragma unroll
    for (int s = 0; s < NSTGA - 1; ++s) {
        int gc = s * 16 + wcol;
        #pragma unroll
        for (int i = 0; i < 4; ++i)
            cp16(smem_u32(&ws4[s][wrow + 16 * i][wcol]),
                 reinterpret_cast<const float4*>(wg) + (size_t)(wrow + 16 * i) * (HID / 4) + gc);
        if (do_x)
            cp16p(smem_u32(&xs4[s][wrow - 8][wcol]), xsrcA + gc, xvalid);
        cp_commit();
    }

    float acc0 = 0.f, acc1 = 0.f;
    #pragma unroll
    for (int c = 0; c < NCI; ++c) {
        int cb = c % NSTGA;
        cp_wait2();
        __syncthreads();
        #pragma unroll
        for (int k = 0; k < 16; ++k) {
            float4 w = ws4[cb][r][k];
            float4 a = xs4[cb][tg][k];
            float4 b = xs4[cb][tg + 4][k];
            acc0 += w.x * a.x + w.y * a.y + w.z * a.z + w.w * a.w;
            acc1 += w.x * b.x + w.y * b.y + w.z * b.z + w.w * b.w;
        }
        if (c + NSTGA - 1 < NCI) {
            int nb = (c + NSTGA - 1) % NSTGA;
            int gc = (c + NSTGA - 1) * 16 + wcol;
            #pragma unroll
            for (int i = 0; i < 4; ++i)
                cp16(smem_u32(&ws4[nb][wrow + 16 * i][wcol]),
                     reinterpret_cast<const float4*>(wg) + (size_t)(wrow + 16 * i) * (HID / 4) + gc);
            if (do_x)
                cp16p(smem_u32(&xs4[nb][wrow - 8][wcol]), xsrcA + gc, xvalid);
        }
        cp_commit();
    }
    lg[tg][r]     = acc0;
    lg[tg + 4][r] = acc1;
    __syncthreads();

    if (t < 8) {
        int token = tok0 + t;
        if (token < bs) {
            g_prog[token] = 0;
            unsigned long long used = 0ULL;
            int sel[4]; float lv[4];
            #pragma unroll
            for (int s = 0; s < 4; ++s) {
                float best = -INFINITY; int bi = 0;
                for (int e = 0; e < NE; ++e) {
                    if ((used >> e) & 1ULL) continue;
                    float v = lg[t][e];
                    if (v > best) { best = v; bi = e; }
                }
                used |= 1ULL << bi;
                sel[s] = bi; lv[s] = best;
            }
            float m  = lv[0];
            float w0 = 1.f;
            float w1 = expf(lv[1] - m);
            float w2 = expf(lv[2] - m);
            float w3 = expf(lv[3] - m);
            float z  = w0 + w1 + w2 + w3;
            w0 /= z; w1 /= z; w2 /= z; w3 /= z;
            float* o = outw + token * 8;
            o[0] = w0; o[1] = w0; o[2] = w0;
            o[3] = w1; o[4] = w1;
            o[5] = w2; o[6] = w2;
            o[7] = w3;
            #pragma unroll
            for (int s = 0; s < 4; ++s) {
                g_slotexp[token * 4 + s] = sel[s];
                g_pcnt[token * 4 + s] = 0;
            }
        }
    }
}

// ============================================================
// Phase B: row-split (gate-half | up-half blocks), per-expert
// scan, 32-token chunks, 3-stage cp.async pipeline with
// issue-early, packed f32x2 FMA; halves rendezvous via g_res,
// second arriver scores + top-3; 4th pair finalizes token.
// ============================================================
__global__ __launch_bounds__(256) void phaseB(const float* __restrict__ x,
                                              const float* __restrict__ gw,
                                              const float* __restrict__ uw,
                                              float* __restrict__ out,
                                              int bs) {
    extern __shared__ char dsm[];
    float4     (*ws4)[32][17] = reinterpret_cast<float4(*)[32][17]>(dsm);
    ulonglong2 (*wsU)[32][17] = reinterpret_cast<ulonglong2(*)[32][17]>(dsm);
    float4     (*xs4)[TB][17] = reinterpret_cast<float4(*)[TB][17]>(dsm + WS_BYTES);
    ulonglong2 (*xsU)[TB][17] = reinterpret_cast<ulonglong2(*)[TB][17]>(dsm + WS_BYTES);
    int*       toklist        = reinterpret_cast<int*>(dsm + WS_BYTES + XS_BYTES);

    __shared__ int s_wsum[8], s_wbase[8], s_cnt;

    int e    = blockIdx.x >> 1;
    int half = blockIdx.x & 1;     // 0: gate rows, 1: up rows
    int t    = threadIdx.x;
    int j    = t & 31;             // local row within half
    int tg   = t >> 5;             // token group: tokens tg+8m
    int lane = t & 31;
    int wid  = t >> 5;

    // ---- deterministic scan of slot->expert map ----
    int flatN = bs * 4;
    int base_i = t * 16;
    int vals[16];
    #pragma unroll
    for (int i = 0; i < 16; i += 4) {
        int4 v4 = make_int4(-1, -1, -1, -1);
        if (base_i + i + 3 < flatN)
            v4 = reinterpret_cast<const int4*>(g_slotexp)[(base_i + i) >> 2];
        vals[i] = v4.x; vals[i + 1] = v4.y; vals[i + 2] = v4.z; vals[i + 3] = v4.w;
    }
    int cl = 0;
    #pragma unroll
    for (int i = 0; i < 16; ++i) cl += (vals[i] == e);
    int pre = cl;
    #pragma unroll
    for (int o = 1; o < 32; o <<= 1) {
        int v = __shfl_up_sync(0xFFFFFFFFu, pre, o);
        if (lane >= o) pre += v;
    }
    if (lane == 31) s_wsum[wid] = pre;
    __syncthreads();
    if (t == 0) {
        int run = 0;
        #pragma unroll
        for (int w = 0; w < 8; ++w) { s_wbase[w] = run; run += s_wsum[w]; }
        s_cnt = run;
    }
    __syncthreads();
    int p = s_wbase[wid] + pre - cl;
    #pragma unroll
    for (int i = 0; i < 16; ++i) {
        if (vals[i] == e && p < EPCAP) toklist[p++] = base_i + i;
    }
    __syncthreads();
    int cnt = s_cnt < EPCAP ? s_cnt : EPCAP;

    // staging maps: w: 256 threads -> 16 rows x 16 cols (2 row blocks)
    int wrow = t >> 4;
    int wcol = t & 15;
    const float* wsel = half ? uw : gw;
    const float4* wsrc[2];
    #pragma unroll
    for (int i = 0; i < 2; ++i)
        wsrc[i] = reinterpret_cast<const float4*>(
            wsel + ((size_t)e * 32 + wrow + 16 * i) * HID);
    // x: 256 threads -> 32 token rows x 8 col-slots (2 cols each)
    int xrow = t >> 3;
    int xc0  = t & 7;

    for (int chunk = blockIdx.y; chunk * TB < cnt; chunk += gridDim.y) {
        int base = chunk * TB;
        int prx = (base + xrow < cnt) ? toklist[base + xrow] : -1;
        const float4* xsrc = reinterpret_cast<const float4*>(x) +
                             (prx >= 0 ? (size_t)(prx >> 2) * (HID / 4) : 0);

        // prologue: issue stages 0..1
        #pragma unroll
        for (int s = 0; s < NSTGB - 1; ++s) {
            int gc = s * 16 + wcol;
            #pragma unroll
            for (int i = 0; i < 2; ++i)
                cp16(smem_u32(&ws4[s][wrow + 16 * i][wcol]), wsrc[i] + gc);
            int gx = s * 16;
            cp16p(smem_u32(&xs4[s][xrow][xc0]), xsrc + gx + xc0, prx >= 0);
            cp16p(smem_u32(&xs4[s][xrow][xc0 + 8]), xsrc + gx + xc0 + 8, prx >= 0);
            cp_commit();
        }

        unsigned long long a[4][2] = {{0,0},{0,0},{0,0},{0,0}};

        #pragma unroll
        for (int c = 0; c < NCI; ++c) {
            int cb = c % NSTGB;
            cp_wait1();                      // stage c complete; c+1 in flight
            __syncthreads();                 // all warps done with buf (c-1)%3
            // issue-early: stage c+2 into buf (c+2)%3 == (c-1)%3 (now free)
            if (c + NSTGB - 1 < NCI) {
                int nb = (c + NSTGB - 1) % NSTGB;
                int gc = (c + NSTGB - 1) * 16 + wcol;
                #pragma unroll
                for (int i = 0; i < 2; ++i)
                    cp16(smem_u32(&ws4[nb][wrow + 16 * i][wcol]), wsrc[i] + gc);
                int gx = (c + NSTGB - 1) * 16;
                cp16p(smem_u32(&xs4[nb][xrow][xc0]), xsrc + gx + xc0, prx >= 0);
                cp16p(smem_u32(&xs4[nb][xrow][xc0 + 8]), xsrc + gx + xc0 + 8, prx >= 0);
            }
            cp_commit();                     // commit (possibly empty) keeps counts aligned
            #pragma unroll
            for (int k = 0; k < 16; ++k) {
                ulonglong2 wv = wsU[cb][j][k];
                #pragma unroll
                for (int m = 0; m < 4; ++m) {
                    ulonglong2 xv = xsU[cb][tg + 8 * m][k];   // warp-broadcast
                    fma2(a[m][0], wv.x, xv.x);
                    fma2(a[m][1], wv.y, xv.y);
                }
            }
        }
        // write this half's 32 rows per pair to global exchange buffer
        #pragma unroll
        for (int m = 0; m < 4; ++m) {
            int idx = base + tg + 8 * m;
            if (idx < cnt) {
                int pr = toklist[idx];
                g_res[(size_t)pr * 64 + half * 32 + j] = unpack_sum(a[m][0], a[m][1]);
            }
        }
        __threadfence();     // release g_res writes (each writer fences its own)
        __syncthreads();     // all writers fenced before any pair atomic below

        // ---- pair rendezvous: second arriver scores + top-3 ----
        if (t < TB) {
            int idx = base + t;
            if (idx < cnt) {
                int pr = toklist[idx];
                int done = atomicAdd(&g_pcnt[pr], 1);
                if (done == 1) {             // both halves complete
                    __threadfence();         // acquire other half's g_res
                    int token = pr >> 2;
                    int slot  = pr & 3;
                    const float* rr = g_res + (size_t)pr * 64;
                    float inner[8];
                    #pragma unroll
                    for (int i = 0; i < 8; ++i) {
                        float s = 0.f;
                        #pragma unroll
                        for (int b = 0; b < 4; ++b) {
                            int jj  = i * 4 + b;
                            float g = rr[jj];
                            float u = rr[32 + jj];
                            float sil = g / (1.f + expf(-g));
                            s += fabsf(u * sil);
                        }
                        inner[i] = s * 0.25f;
                    }
                    int keep = (slot == 0) ? 3 : ((slot == 3) ? 1 : 2);  // (3,2,2,1)
                    int outb = token * 12 + slot * 3;
                    unsigned used = 0;
                    #pragma unroll
                    for (int jj = 0; jj < 3; ++jj) {
                        float best = -INFINITY; int bi = 0;
                        #pragma unroll
                        for (int i = 0; i < 8; ++i) {
                            if ((used >> i) & 1u) continue;
                            if (inner[i] > best) { best = inner[i]; bi = i; }
                        }
                        used |= 1u << bi;
                        g_ids[outb + jj] = (jj < keep) ? (e * 8 + bi) : -10000;
                    }
                    __threadfence();
                    int tdone = atomicAdd(&g_prog[token], 1);
                    if (tdone == 3) {        // 4th pair finalizes token
                        __threadfence();
                        int v[12];
                        #pragma unroll
                        for (int i = 0; i < 12; ++i) v[i] = g_ids[token * 12 + i];
                        #pragma unroll
                        for (int i = 1; i < 12; ++i) {
                            int key = v[i], j2 = i - 1;
                            while (j2 >= 0 && v[j2] < key) { v[j2 + 1] = v[j2]; --j2; }
                            v[j2 + 1] = key;
                        }
                        #pragma unroll
                        for (int i = 0; i < 8; ++i)
                            out[token * 8 + i] = (float)v[i];
                    }
                }
            }
        }
        __syncthreads();   // protect ws/xs buffers before next chunk prologue
    }
}

extern "C" void kernel_launch(void* const* d_in, const int* in_sizes, int n_in,
                              void* d_out, int out_size) {
    const float* x  = (const float*)d_in[0];
    const float* wg = (const float*)d_in[1];
    const float* gw = (const float*)d_in[2];
    const float* uw = (const float*)d_in[3];
    float* out = (float*)d_out;

    int bs = in_sizes[0] / HID;
    if (bs > MAXBS) bs = MAXBS;

    cudaFuncSetAttribute(phaseA, cudaFuncAttributeMaxDynamicSharedMemorySize, SMEM_A);
    cudaFuncSetAttribute(phaseB, cudaFuncAttributeMaxDynamicSharedMemorySize, SMEM_B);

    phaseA<<<(bs + 7) / 8, 256, SMEM_A>>>(x, wg, out + bs * 8, bs);
    phaseB<<<dim3(NE * 2, GRIDY), 256, SMEM_B>>>(x, gw, uw, out, bs);
}

// round 13
// speedup vs baseline: 2.1469x; 2.1469x over previous
#include <cuda_runtime.h>
#include <stdint.h>
#include <math.h>

#define HID 1024
#define NE 64
#define MAXBS 1024
#define EPCAP 1024
#define TB 16            // tokens per phaseB chunk
#define KCB 64           // hidden-dim per pipeline stage
#define NCI (HID / KCB)  // 16 stages per chunk
#define NSTG 4           // pipeline depth (lookahead = 2 stages)

// phaseB dynamic smem layout (bytes)
#define WS_BYTES (NSTG * 64 * 17 * 16)          // 69632
#define XS_BYTES (NSTG * TB * 17 * 16)          // 17408
#define RES_BYTES (TB * 65 * 4)                 // 4160
#define TL_BYTES (EPCAP * 4)                    // 4096
#define SMEM_B (WS_BYTES + XS_BYTES + RES_BYTES + TL_BYTES)

// phaseA dynamic smem layout (bytes)
#define WSA_BYTES (NSTG * 64 * 17 * 16)         // 69632
#define XSA_BYTES (NSTG * 8 * 17 * 16)          // 8704
#define LG_BYTES  (8 * 64 * 4)                  // 2048
#define SMEM_A (WSA_BYTES + XSA_BYTES + LG_BYTES)

// ---- device scratch (allocation-free) ----
__device__ int g_slotexp[MAXBS * 4];  // [token*4+slot] -> expert id
__device__ int g_prog[MAXBS];         // completion counter per token
__device__ int g_ids[MAXBS * 12];     // per-token candidate ids (masked = -10000)

__device__ __forceinline__ void cp16(unsigned int dst, const void* src) {
    asm volatile("cp.async.cg.shared.global [%0], [%1], 16;" :: "r"(dst), "l"(src));
}
__device__ __forceinline__ void cp16p(unsigned int dst, const void* src, int valid) {
    asm volatile("cp.async.cg.shared.global [%0], [%1], 16, %2;"
                 :: "r"(dst), "l"(src), "r"(valid ? 16 : 0));
}
__device__ __forceinline__ void cp_commit() { asm volatile("cp.async.commit_group;"); }
__device__ __forceinline__ void cp_wait2() { asm volatile("cp.async.wait_group 2;"); }
__device__ __forceinline__ unsigned int smem_u32(const void* p) {
    return (unsigned int)__cvta_generic_to_shared(p);
}
// packed f32x2 fma: acc += a * b (elementwise on 2 packed floats)
__device__ __forceinline__ void fma2(unsigned long long& acc,
                                     unsigned long long a, unsigned long long b) {
    asm("fma.rn.f32x2 %0, %1, %2, %0;" : "+l"(acc) : "l"(a), "l"(b));
}
__device__ __forceinline__ float unpack_sum(unsigned long long lo, unsigned long long hi) {
    float s0, s1, s2, s3;
    asm("mov.b64 {%0,%1}, %2;" : "=f"(s0), "=f"(s1) : "l"(lo));
    asm("mov.b64 {%0,%1}, %2;" : "=f"(s2), "=f"(s3) : "l"(hi));
    return (s0 + s1) + (s2 + s3);
}

// ============================================================
// Phase A: router GEMM (8 tokens/block) with 4-stage cp.async
// pipeline; top-4 + renorm weights; writes final_weights,
// slot->expert map, zeroes g_prog.
// ============================================================
__global__ __launch_bounds__(256) void phaseA(const float* __restrict__ x,
                                              const float* __restrict__ wg,
                                              float* __restrict__ outw,
                                              int bs) {
    extern __shared__ char dsa[];
    float4 (*ws4)[64][17] = reinterpret_cast<float4(*)[64][17]>(dsa);
    float4 (*xs4)[8][17]  = reinterpret_cast<float4(*)[8][17]>(dsa + WSA_BYTES);
    float  (*lg)[64]      = reinterpret_cast<float(*)[64]>(dsa + WSA_BYTES + XSA_BYTES);

    int t  = threadIdx.x;
    int r  = t & 63;
    int tg = t >> 6;
    int tok0 = blockIdx.x * 8;

    int wrow = t >> 4;
    int wcol = t & 15;
    int xtok = tok0 + wrow - 8;
    int do_x = (wrow >= 8) && (wrow < 16);
    const float4* xsrcA = reinterpret_cast<const float4*>(x) +
        ((do_x && xtok < bs) ? (size_t)xtok * (HID / 4) : 0);
    int xvalid = do_x && (xtok < bs);

    #pragma unroll
    for (int s = 0; s < NSTG - 1; ++s) {
        int gc = s * 16 + wcol;
        #pragma unroll
        for (int i = 0; i < 4; ++i)
            cp16(smem_u32(&ws4[s][wrow + 16 * i][wcol]),
                 reinterpret_cast<const float4*>(wg) + (size_t)(wrow + 16 * i) * (HID / 4) + gc);
        if (do_x)
            cp16p(smem_u32(&xs4[s][wrow - 8][wcol]), xsrcA + gc, xvalid);
        cp_commit();
    }

    float acc0 = 0.f, acc1 = 0.f;
    #pragma unroll
    for (int c = 0; c < NCI; ++c) {
        int cb = c % NSTG;
        cp_wait2();
        __syncthreads();
        #pragma unroll
        for (int k = 0; k < 16; ++k) {
            float4 w = ws4[cb][r][k];
            float4 a = xs4[cb][tg][k];
            float4 b = xs4[cb][tg + 4][k];
            acc0 += w.x * a.x + w.y * a.y + w.z * a.z + w.w * a.w;
            acc1 += w.x * b.x + w.y * b.y + w.z * b.z + w.w * b.w;
        }
        if (c + NSTG - 1 < NCI) {
            int nb = (c + NSTG - 1) % NSTG;
            int gc = (c + NSTG - 1) * 16 + wcol;
            #pragma unroll
            for (int i = 0; i < 4; ++i)
                cp16(smem_u32(&ws4[nb][wrow + 16 * i][wcol]),
                     reinterpret_cast<const float4*>(wg) + (size_t)(wrow + 16 * i) * (HID / 4) + gc);
            if (do_x)
                cp16p(smem_u32(&xs4[nb][wrow - 8][wcol]), xsrcA + gc, xvalid);
        }
        cp_commit();
    }
    lg[tg][r]     = acc0;
    lg[tg + 4][r] = acc1;
    __syncthreads();

    if (t < 8) {
        int token = tok0 + t;
        if (token < bs) {
            g_prog[token] = 0;
            unsigned long long used = 0ULL;
            int sel[4]; float lv[4];
            #pragma unroll
            for (int s = 0; s < 4; ++s) {
                float best = -INFINITY; int bi = 0;
                for (int e = 0; e < NE; ++e) {
                    if ((used >> e) & 1ULL) continue;
                    float v = lg[t][e];
                    if (v > best) { best = v; bi = e; }
                }
                used |= 1ULL << bi;
                sel[s] = bi; lv[s] = best;
            }
            float m  = lv[0];
            float w0 = 1.f;
            float w1 = expf(lv[1] - m);
            float w2 = expf(lv[2] - m);
            float w3 = expf(lv[3] - m);
            float z  = w0 + w1 + w2 + w3;
            w0 /= z; w1 /= z; w2 /= z; w3 /= z;
            float* o = outw + token * 8;
            o[0] = w0; o[1] = w0; o[2] = w0;
            o[3] = w1; o[4] = w1;
            o[5] = w2; o[6] = w2;
            o[7] = w3;
            #pragma unroll
            for (int s = 0; s < 4; ++s)
                g_slotexp[token * 4 + s] = sel[s];
        }
    }
}

// ============================================================
// Phase B: per-expert scan+group, 16-token chunks, 4-stage
// cp.async pipeline (lookahead 2), gate/up matvecs with packed
// f32x2 FMA, silu scores, top-3, fused final sort+write.
// (R7 structure; only the inner compute is packed.)
// ============================================================
__global__ __launch_bounds__(256) void phaseB(const float* __restrict__ x,
                                              const float* __restrict__ gw,
                                              const float* __restrict__ uw,
                                              float* __restrict__ out,
                                              int bs) {
    extern __shared__ char dsm[];
    float4     (*ws4)[64][17] = reinterpret_cast<float4(*)[64][17]>(dsm);
    ulonglong2 (*wsU)[64][17] = reinterpret_cast<ulonglong2(*)[64][17]>(dsm);
    float4     (*xs4)[TB][17] = reinterpret_cast<float4(*)[TB][17]>(dsm + WS_BYTES);
    ulonglong2 (*xsU)[TB][17] = reinterpret_cast<ulonglong2(*)[TB][17]>(dsm + WS_BYTES);
    float      (*res)[65]     = reinterpret_cast<float(*)[65]>(dsm + WS_BYTES + XS_BYTES);
    int*       toklist        = reinterpret_cast<int*>(dsm + WS_BYTES + XS_BYTES + RES_BYTES);

    __shared__ int s_wsum[8], s_wbase[8], s_cnt;

    int e    = blockIdx.x;
    int t    = threadIdx.x;
    int r    = t & 63;       // output row (0-31 gate, 32-63 up)
    int tg   = t >> 6;       // tokens tg, tg+4, tg+8, tg+12
    int lane = t & 31;
    int wid  = t >> 5;

    // ---- deterministic scan of slot->expert map ----
    int flatN = bs * 4;
    int base_i = t * 16;
    int vals[16];
    #pragma unroll
    for (int i = 0; i < 16; i += 4) {
        int4 v4 = make_int4(-1, -1, -1, -1);
        if (base_i + i + 3 < flatN)
            v4 = reinterpret_cast<const int4*>(g_slotexp)[(base_i + i) >> 2];
        vals[i] = v4.x; vals[i + 1] = v4.y; vals[i + 2] = v4.z; vals[i + 3] = v4.w;
    }
    int cl = 0;
    #pragma unroll
    for (int i = 0; i < 16; ++i) cl += (vals[i] == e);
    int pre = cl;
    #pragma unroll
    for (int o = 1; o < 32; o <<= 1) {
        int v = __shfl_up_sync(0xFFFFFFFFu, pre, o);
        if (lane >= o) pre += v;
    }
    if (lane == 31) s_wsum[wid] = pre;
    __syncthreads();
    if (t == 0) {
        int run = 0;
        #pragma unroll
        for (int w = 0; w < 8; ++w) { s_wbase[w] = run; run += s_wsum[w]; }
        s_cnt = run;
    }
    __syncthreads();
    int p = s_wbase[wid] + pre - cl;
    #pragma unroll
    for (int i = 0; i < 16; ++i) {
        if (vals[i] == e && p < EPCAP) toklist[p++] = base_i + i;
    }
    __syncthreads();
    int cnt = s_cnt < EPCAP ? s_cnt : EPCAP;

    // staging maps: 256 threads -> 16 rows x 16 cols
    int wrow = t >> 4;
    int wcol = t & 15;
    const float4* wsrc[4];
    #pragma unroll
    for (int i = 0; i < 4; ++i) {
        int row = wrow + 16 * i;
        const float* s = (row < 32) ? gw + ((size_t)e * 32 + row) * HID
                                    : uw + ((size_t)e * 32 + (row - 32)) * HID;
        wsrc[i] = reinterpret_cast<const float4*>(s);
    }

    for (int chunk = blockIdx.y; chunk * TB < cnt; chunk += gridDim.y) {
        int base = chunk * TB;
        int prx = (base + wrow < cnt) ? toklist[base + wrow] : -1;
        const float4* xsrc = reinterpret_cast<const float4*>(x) +
                             (prx >= 0 ? (size_t)(prx >> 2) * (HID / 4) : 0);

        // prologue: issue stages 0..2
        #pragma unroll
        for (int s = 0; s < NSTG - 1; ++s) {
            int gc = s * 16 + wcol;
            #pragma unroll
            for (int i = 0; i < 4; ++i)
                cp16(smem_u32(&ws4[s][wrow + 16 * i][wcol]), wsrc[i] + gc);
            cp16p(smem_u32(&xs4[s][wrow][wcol]), xsrc + gc, prx >= 0);
            cp_commit();
        }

        // packed accumulators: [token m][lo/hi]
        unsigned long long a[4][2] = {{0,0},{0,0},{0,0},{0,0}};

        #pragma unroll
        for (int c = 0; c < NCI; ++c) {
            int cb = c % NSTG;
            cp_wait2();                      // stage c done; c+1,c+2 in flight
            __syncthreads();
            #pragma unroll
            for (int k = 0; k < 16; ++k) {
                ulonglong2 wv = wsU[cb][r][k];
                #pragma unroll
                for (int m = 0; m < 4; ++m) {
                    ulonglong2 xv = xsU[cb][tg + 4 * m][k];   // warp-broadcast
                    fma2(a[m][0], wv.x, xv.x);
                    fma2(a[m][1], wv.y, xv.y);
                }
            }
            if (c + NSTG - 1 < NCI) {        // issue stage c+3 into buf (c+3)%4
                int nb = (c + NSTG - 1) % NSTG;
                int gc = (c + NSTG - 1) * 16 + wcol;
                #pragma unroll
                for (int i = 0; i < 4; ++i)
                    cp16(smem_u32(&ws4[nb][wrow + 16 * i][wcol]), wsrc[i] + gc);
                cp16p(smem_u32(&xs4[nb][wrow][wcol]), xsrc + gc, prx >= 0);
            }
            cp_commit();                     // keep group counts aligned
        }
        #pragma unroll
        for (int m = 0; m < 4; ++m)
            res[tg + 4 * m][r] = unpack_sum(a[m][0], a[m][1]);
        __syncthreads();

        // ---- scoring + inner top-3 + fused finalize ----
        if (t < TB) {
            int pr = (base + t < cnt) ? toklist[base + t] : -1;
            if (pr >= 0) {
                int token = pr >> 2;
                int slot  = pr & 3;
                float inner[8];
                #pragma unroll
                for (int i = 0; i < 8; ++i) {
                    float s = 0.f;
                    #pragma unroll
                    for (int b = 0; b < 4; ++b) {
                        int j   = i * 4 + b;
                        float g = res[t][j];
                        float u = res[t][32 + j];
                        float sil = g / (1.f + expf(-g));
                        s += fabsf(u * sil);
                    }
                    inner[i] = s * 0.25f;
                }
                int keep = (slot == 0) ? 3 : ((slot == 3) ? 1 : 2);  // pattern (3,2,2,1)
                int outb = token * 12 + slot * 3;
                unsigned used = 0;
                #pragma unroll
                for (int jj = 0; jj < 3; ++jj) {
                    float best = -INFINITY; int bi = 0;
                    #pragma unroll
                    for (int i = 0; i < 8; ++i) {
                        if ((used >> i) & 1u) continue;
                        if (inner[i] > best) { best = inner[i]; bi = i; }
                    }
                    used |= 1u << bi;
                    g_ids[outb + jj] = (jj < keep) ? (e * 8 + bi) : -10000;
                }
                __threadfence();
                int done = atomicAdd(&g_prog[token], 1);
                if (done == 3) {
                    __threadfence();
                    int v[12];
                    #pragma unroll
                    for (int i = 0; i < 12; ++i) v[i] = g_ids[token * 12 + i];
                    #pragma unroll
                    for (int i = 1; i < 12; ++i) {
                        int key = v[i], j2 = i - 1;
                        while (j2 >= 0 && v[j2] < key) { v[j2 + 1] = v[j2]; --j2; }
                        v[j2 + 1] = key;
                    }
                    #pragma unroll
                    for (int i = 0; i < 8; ++i)
                        out[token * 8 + i] = (float)v[i];
                }
            }
        }
        __syncthreads();   // protect buffers + toklist before next chunk
    }
}

extern "C" void kernel_launch(void* const* d_in, const int* in_sizes, int n_in,
                              void* d_out, int out_size) {
    const float* x  = (const float*)d_in[0];
    const float* wg = (const float*)d_in[1];
    const float* gw = (const float*)d_in[2];
    const float* uw = (const float*)d_in[3];
    float* out = (float*)d_out;

    int bs = in_sizes[0] / HID;
    if (bs > MAXBS) bs = MAXBS;

    cudaFuncSetAttribute(phaseA, cudaFuncAttributeMaxDynamicSharedMemorySize, SMEM_A);
    cudaFuncSetAttribute(phaseB, cudaFuncAttributeMaxDynamicSharedMemorySize, SMEM_B);

    phaseA<<<(bs + 7) / 8, 256, SMEM_A>>>(x, wg, out + bs * 8, bs);
    phaseB<<<dim3(NE, 6), 256, SMEM_B>>>(x, gw, uw, out, bs);
}